// round 17
// baseline (speedup 1.0000x reference)
#include <cuda_runtime.h>

#define NB 4
#define DK 256
#define DV 516
#define HW 4096
#define HWC 2048        // hw per pipeline chunk (2 chunks x 2 streams)
#define LM 32
#define DSP 2           // d sub-splits in score phase (32 d each)
#define DQ 4            // d-splits across gridDim.y (64 d per block)

#define CCH 14          // out c-chunk: 37 chunks
#define NCH 37
#define OST 6           // out cp.async ring stages

// temp = log2(32*64*64 + 64*64) / sqrt(256)
#define TEMP 1.06527463f

// packed f32x2 FMA: d = a*b + d, lane-wise (2 independent IEEE fp32 fmas)
#define FMA_F32X2(d, a, b) \
    asm("fma.rn.f32x2 %0, %1, %2, %0;" : "+l"(d) : "l"(a), "l"(b))
// duplicate one fp32 into both lanes of a 64-bit packed register
#define PACK_DUP_F32X2(out, f) \
    asm("mov.b64 %0, {%1, %1};" : "=l"(out) : "r"(__float_as_uint(f)))

// cp.async: 16B global->shared, scoreboard-free
#define CP_ASYNC16(dst_u32, src_ptr) \
    asm volatile("cp.async.cg.shared.global [%0], [%1], 16;" \
                 :: "r"(dst_u32), "l"(src_ptr))
#define CP_ASYNC_COMMIT() asm volatile("cp.async.commit_group;")
#define CP_ASYNC_WAIT(n)  asm volatile("cp.async.wait_group %0;" :: "n"(n))

typedef unsigned long long ull;

// Scratch (static device allocations only; no cudaMalloc anywhere)
__device__ float g_attn[NB * LM * HW];         // 2 MB:  attn[b][m][hw]
__device__ float g_part[DQ * NB * LM * HW];    // 8 MB:  partial scores

// ---------------------------------------------------------------------------
// FUSED kernel: qproj GEMM + partial scores in one kernel.
// Grid (HWC/64, DQ), block 256, dyn smem 75776 B:
//   [0:512)      Qs[8][64]        (c-tile of Q columns for this dq slice)
//   [512:2560)   Fs[4][8][64]     (c-tile of fc for 4 batches, 64 hw)
//   [2560:18944) qs[4][64][64]    (computed q tile, TEMP-scaled)
//   s_red aliases offset 0 (64KB) AFTER phase 2 (sync-fenced).
// Phase 1: q[b][d][hw] = TEMP * sum_c fc[b][c][hw] * Q[c][dq*64+d]
//   thread (tx=hw/4, ty=d/4) computes 4d x 4hw x 4b via FFMA2 (hw pairs);
//   ascending-c accumulation -> bit-identical to the old qproj.
// Phase 2: scores vs key (hw-pairs, LDG.64 + FMA2), q read from smem.
// The qproj FMA work now executes inside the DRAM-bound score kernel ->
// guaranteed compute/memory overlap; g_q (32MB traffic) eliminated.
// ---------------------------------------------------------------------------
__global__ __launch_bounds__(256, 2) void attn_fused_kernel(
    const float* __restrict__ fc, const float* __restrict__ Qm,
    const float* __restrict__ key, int hwb) {
    extern __shared__ float sm[];
    float* Qs = sm;                 // [8][64]
    float* Fs = sm + 512;           // [4][8][64]
    float* qs = sm + 2560;          // [4][64][64]
    float* s_red = sm;              // alias: [DSP][LM][NB][64] (64KB)

    const int tid = threadIdx.x;
    const int dq  = blockIdx.y;
    const int hw0 = hwb + blockIdx.x * 64;

    // ================= phase 1: q-tile GEMM =================
    {
        const int tx = tid & 15;    // hw quad (4 hw)
        const int ty = tid >> 4;    // d quad (4 d)

        ull acc2[4][4][2];          // [b][d][hw-pair]
#pragma unroll
        for (int b = 0; b < 4; b++)
#pragma unroll
            for (int i = 0; i < 4; i++) { acc2[b][i][0] = 0ull; acc2[b][i][1] = 0ull; }

        for (int k0 = 0; k0 < DK; k0 += 8) {
            __syncthreads();   // prior compute done reading staging
            // load Qs: 8 rows x 64 d-cols, float2 per thread
            {
                const int r   = tid >> 5;
                const int col = (tid & 31) * 2;
                *(float2*)&Qs[r * 64 + col] =
                    *(const float2*)(Qm + (size_t)(k0 + r) * DK + dq * 64 + col);
            }
            // load Fs: 4b x 8c x 64hw, 2 float4 per thread, coalesced
#pragma unroll
            for (int s = 0; s < 2; s++) {
                const int u  = s * 256 + tid;
                const int b  = u >> 7;
                const int rc = (u >> 4) & 7;
                const int l4 = u & 15;
                *(float4*)&Fs[(b * 8 + rc) * 64 + l4 * 4] =
                    *(const float4*)(fc + (size_t)b * DK * HW +
                                     (size_t)(k0 + rc) * HW + hw0 + l4 * 4);
            }
            __syncthreads();

#pragma unroll
            for (int k = 0; k < 8; k++) {
                float a4[4];
                *(float4*)a4 = *(const float4*)&Qs[k * 64 + ty * 4];
#pragma unroll
                for (int b = 0; b < 4; b++) {
                    ull f0 = *(const ull*)&Fs[(b * 8 + k) * 64 + tx * 4];
                    ull f1 = *(const ull*)&Fs[(b * 8 + k) * 64 + tx * 4 + 2];
#pragma unroll
                    for (int i = 0; i < 4; i++) {
                        ull a2;
                        PACK_DUP_F32X2(a2, a4[i]);
                        FMA_F32X2(acc2[b][i][0], a2, f0);
                        FMA_F32X2(acc2[b][i][1], a2, f1);
                    }
                }
            }
        }

        // store q tile (TEMP-scaled). qs disjoint from staging -> no sync needed.
#pragma unroll
        for (int b = 0; b < 4; b++)
#pragma unroll
            for (int i = 0; i < 4; i++)
#pragma unroll
                for (int p = 0; p < 2; p++) {
                    const float* af = (const float*)&acc2[b][i][p];
                    float2 v;
                    v.x = af[0] * TEMP;
                    v.y = af[1] * TEMP;
                    *(float2*)&qs[((b * 64) + ty * 4 + i) * 64 + tx * 4 + p * 2] = v;
                }
    }
    __syncthreads();   // q tile complete & visible

    // ================= phase 2: partial scores =================
    {
        const int lane = tid & 31;           // hw pair index
        const int ms   = (tid >> 5) & 3;     // m group (8 m)
        const int ds   = tid >> 7;           // d sub-split (32 d each)
        const int hw2  = hw0 + lane * 2;

        const float* kp[8];
#pragma unroll
        for (int j = 0; j < 8; j++)
            kp[j] = key + (size_t)(ms * 8 + j) * DK * HW +
                    (size_t)(dq * 64 + ds * 32) * HW + hw2;

        const float* qbase = qs + (size_t)(ds * 32) * 64 + lane * 2;

        ull acc2[NB][8];
#pragma unroll
        for (int b = 0; b < NB; b++)
#pragma unroll
            for (int j = 0; j < 8; j++) acc2[b][j] = 0ull;

        for (int d = 0; d < 32; d += 4) {
#pragma unroll
            for (int u = 0; u < 4; u++) {
                ull q2[NB];
#pragma unroll
                for (int b = 0; b < NB; b++)
                    q2[b] = *(const ull*)(qbase + ((size_t)b * 64 + d + u) * 64);
#pragma unroll
                for (int j = 0; j < 8; j++) {
                    const ull k2 = *(const ull*)(kp[j] + (size_t)(d + u) * HW);
                    FMA_F32X2(acc2[0][j], q2[0], k2);
                    FMA_F32X2(acc2[1][j], q2[1], k2);
                    FMA_F32X2(acc2[2][j], q2[2], k2);
                    FMA_F32X2(acc2[3][j], q2[3], k2);
                }
            }
        }

        __syncthreads();   // all qs reads done before s_red overwrites it

        // stash partials: s_red[ds][m][b][2*lane .. 2*lane+1]
#pragma unroll
        for (int b = 0; b < NB; b++)
#pragma unroll
            for (int j = 0; j < 8; j++)
                *(ull*)&s_red[(((ds * LM) + ms * 8 + j) * NB + b) * 64 + 2 * lane] =
                    acc2[b][j];
    }
    __syncthreads();

    // reduce ds and write: 256 threads = 64 hw x 4 b
    {
        const int l   = tid & 63;
        const int b   = tid >> 6;
        const int hwg = hw0 + l;
        float* pp = g_part + (((size_t)blockIdx.y * NB + b) * LM) * HW + hwg;
#pragma unroll
        for (int m = 0; m < LM; m++) {
            const float v = s_red[((0 * LM + m) * NB + b) * 64 + l]
                          + s_red[((1 * LM + m) * NB + b) * 64 + l];
            pp[(size_t)m * HW] = v;
        }
    }
}

// ---------------------------------------------------------------------------
// Kernel 2b v2: finish — dq-parallel partial loads, smem reduce, softmax.
// Block 512 = 32 hw x 4 b x 4 dq-threads. Grid HWC/32. smem 64KB.
// ---------------------------------------------------------------------------
__global__ __launch_bounds__(512) void attn_finish_kernel(int hwb) {
    extern __shared__ float sf[];    // [DQ][NB][LM][32] = 64KB

    const int tid = threadIdx.x;
    const int l   = tid & 31;
    const int b   = (tid >> 5) & 3;
    const int dqt = tid >> 7;
    const int hw  = hwb + blockIdx.x * 32 + l;

    {
        const float* pp = g_part + (((size_t)dqt * NB + b) * LM) * HW + hw;
        float* dst = &sf[((dqt * NB + b) * LM) * 32 + l];
#pragma unroll
        for (int m = 0; m < LM; m++)
            dst[m * 32] = pp[(size_t)m * HW];
    }
    __syncthreads();

    if (tid < 128) {
        const int bb  = tid >> 5;
        const int ll  = tid & 31;
        const int hwg = hwb + blockIdx.x * 32 + ll;
        float s[LM];
        float mx = -1e30f;
#pragma unroll
        for (int m = 0; m < LM; m++) {
            const float v = sf[((0 * NB + bb) * LM + m) * 32 + ll]
                          + sf[((1 * NB + bb) * LM + m) * 32 + ll]
                          + sf[((2 * NB + bb) * LM + m) * 32 + ll]
                          + sf[((3 * NB + bb) * LM + m) * 32 + ll];
            s[m] = v;
            mx = fmaxf(mx, v);
        }
        float sum = 0.0f;
#pragma unroll
        for (int m = 0; m < LM; m++) { s[m] = __expf(s[m] - mx); sum += s[m]; }
        const float inv = 1.0f / sum;
        float* ap = g_attn + (size_t)bb * LM * HW + hwg;
#pragma unroll
        for (int m = 0; m < LM; m++) ap[(size_t)m * HW] = s[m] * inv;
    }
}

// ---------------------------------------------------------------------------
// Kernel 3 v7: out via 6-stage cp.async ring, one barrier per c-iteration.
// Grid (HWC/128, 37) = 592 blocks = exactly 2.0 waves at 2 blocks/SM.
// ---------------------------------------------------------------------------
__global__ __launch_bounds__(256, 2) void out_kernel(
    const float* __restrict__ fm, const float* __restrict__ val,
    float* __restrict__ out, int hwb) {
    extern __shared__ float vs[];       // [OST][LM][128] = 96KB ring

    const int tid = threadIdx.x;
    const int hwl = tid & 127;
    const int bg  = tid >> 7;
    const int hw0 = hwb + blockIdx.x * 128;
    const int hw  = hw0 + hwl;
    const int c0  = blockIdx.y * CCH;
    const int nc  = (c0 + CCH < DV) ? CCH : (DV - c0);
    const int b0  = bg * 2;
    const int b1  = b0 + 1;

    float a0[LM], a1[LM];
    {
        const float* ap0 = g_attn + (size_t)b0 * LM * HW + hw;
        const float* ap1 = g_attn + (size_t)b1 * LM * HW + hw;
#pragma unroll
        for (int m = 0; m < LM; m++) {
            a0[m] = ap0[(size_t)m * HW];
            a1[m] = ap1[(size_t)m * HW];
        }
    }

    const unsigned vs_base = (unsigned)__cvta_generic_to_shared(vs);
    const float* vsrc0 = val + hw0;

#define OUT_ISSUE_STAGE(stage, c)                                          \
    do {                                                                   \
        const float* _sb = vsrc0 + (size_t)(c) * HW;                       \
        _Pragma("unroll")                                                  \
        for (int _s = 0; _s < 4; _s++) {                                   \
            const int _idx = _s * 256 + tid;                               \
            const int _m   = _idx >> 5;                                    \
            const int _l4  = _idx & 31;                                    \
            const float* _src = _sb + (size_t)_m * DV * HW + _l4 * 4;      \
            const unsigned _dst = vs_base +                                \
                (((stage) * LM + _m) * 128 + _l4 * 4) * 4u;                \
            CP_ASYNC16(_dst, _src);                                        \
        }                                                                  \
        CP_ASYNC_COMMIT();                                                 \
    } while (0)

    OUT_ISSUE_STAGE(0, c0);
    OUT_ISSUE_STAGE(1, c0 + 1);
    OUT_ISSUE_STAGE(2, c0 + 2);

    const float* fmp0 = fm + (size_t)b0 * DV * HW + hw;
    const float* fmp1 = fm + (size_t)b1 * DV * HW + hw;
    float*       op0  = out + (size_t)b0 * DV * HW + hw;
    float*       op1  = out + (size_t)b1 * DV * HW + hw;

    int stage = 0;                       // = cc % OST
    for (int cc = 0; cc < nc; cc++) {
        if (cc + 3 < nc) {
            int istage = stage + 3; if (istage >= OST) istage -= OST;
            OUT_ISSUE_STAGE(istage, c0 + cc + 3);
            CP_ASYNC_WAIT(3);
        } else {
            const int rem = nc - 1 - cc;          // 2, 1, 0
            if (rem == 2)      CP_ASYNC_WAIT(2);
            else if (rem == 1) CP_ASYNC_WAIT(1);
            else               CP_ASYNC_WAIT(0);
        }
        __syncthreads();   // stage-cc writes visible; bounds warp skew

        const int c = c0 + cc;
        const float* vrow = vs + (size_t)stage * LM * 128 + hwl;
        float s0 = 0.0f, s1 = 0.0f, t0 = 0.0f, t1 = 0.0f;
#pragma unroll
        for (int m = 0; m < LM; m += 2) {
            const float v0 = vrow[(size_t)m * 128];
            const float v1 = vrow[(size_t)(m + 1) * 128];
            s0 += a0[m] * v0;     t0 += a1[m] * v0;
            s1 += a0[m + 1] * v1; t1 += a1[m + 1] * v1;
        }
        op0[(size_t)c * HW] = fmp0[(size_t)c * HW] + 0.5f * (s0 + s1);
        op1[(size_t)c * HW] = fmp1[(size_t)c * HW] + 0.5f * (t0 + t1);

        if (++stage == OST) stage = 0;
    }
#undef OUT_ISSUE_STAGE
}

// ---------------------------------------------------------------------------
// Launch: 2-chunk x 2-stream pipeline; per chunk: fused -> finish -> out.
// Chunk 1's fused (compute-bound) overlaps chunk 0's out (DRAM-bound) —
// now exactly complementary phases. Streams/events lazily created on the
// first (uncaptured) call; fork/join events become graph edges.
// Inputs (metadata order): fc, fm, key_buffer, value_buffer, Q, K, V.
// concat(new, buffer)[-32:] keeps exactly the buffers -> K and V matrices are
// dead inputs; only q = fc@Q survives.
// ---------------------------------------------------------------------------
extern "C" void kernel_launch(void* const* d_in, const int* in_sizes, int n_in,
                              void* d_out, int out_size) {
    const float* fc   = (const float*)d_in[0];
    const float* fm   = (const float*)d_in[1];
    const float* keyb = (const float*)d_in[2];
    const float* valb = (const float*)d_in[3];
    const float* Qm   = (const float*)d_in[4];
    float* out = (float*)d_out;

    static cudaStream_t s1 = nullptr;
    static cudaEvent_t  eA = nullptr, eJ = nullptr;
    if (s1 == nullptr) {
        cudaStreamCreateWithFlags(&s1, cudaStreamNonBlocking);
        cudaEventCreateWithFlags(&eA, cudaEventDisableTiming);
        cudaEventCreateWithFlags(&eJ, cudaEventDisableTiming);
    }

    const int fus_bytes = 18944 * sizeof(float);               // 75776 B
    const int fin_bytes = DQ * NB * LM * 32 * sizeof(float);   // 64KB
    const int out_bytes = OST * LM * 128 * sizeof(float);      // 96KB
    cudaFuncSetAttribute(attn_fused_kernel,
                         cudaFuncAttributeMaxDynamicSharedMemorySize, fus_bytes);
    cudaFuncSetAttribute(attn_finish_kernel,
                         cudaFuncAttributeMaxDynamicSharedMemorySize, fin_bytes);
    cudaFuncSetAttribute(out_kernel,
                         cudaFuncAttributeMaxDynamicSharedMemorySize, out_bytes);

    // ---- chunk 0 chain on default stream ----
    attn_fused_kernel<<<dim3(HWC / 64, DQ), 256, fus_bytes, 0>>>(fc, Qm, keyb, 0);
    cudaEventRecord(eA, 0);   // stagger marker
    attn_finish_kernel<<<dim3(HWC / 32), 512, fin_bytes, 0>>>(0);
    out_kernel<<<dim3(HWC / 128, NCH), 256, out_bytes, 0>>>(fm, valb, out, 0);

    // ---- chunk 1 chain on side stream, staggered ----
    cudaStreamWaitEvent(s1, eA, 0);
    attn_fused_kernel<<<dim3(HWC / 64, DQ), 256, fus_bytes, s1>>>(fc, Qm, keyb, HWC);
    attn_finish_kernel<<<dim3(HWC / 32), 512, fin_bytes, s1>>>(HWC);
    out_kernel<<<dim3(HWC / 128, NCH), 256, out_bytes, s1>>>(fm, valb, out, HWC);

    // ---- join back to default stream ----
    cudaEventRecord(eJ, s1);
    cudaStreamWaitEvent((cudaStream_t)0, eJ, 0);
}